// round 4
// baseline (speedup 1.0000x reference)
#include <cuda_runtime.h>
#include <cstdint>

#define GN   8192
#define LMBD 0.1f
#define QCAP 128   // per-warp nonzero queue; E[nnz/warp]=20.5, P(>127) ~ 0

__device__ float    g_sum;     // zero-init; reset by last block each launch
__device__ unsigned g_count;

// One block per row of A (8192 x 256). Warp w owns cols [w*1024,(w+1)*1024).
// Nonzeros are compacted into a per-warp smem queue, then drained 4-at-a-time:
// the warp's 4 groups of 8 lanes each compute one dot Y[i].W[j] (lane holds 16
// elems strided by 8 float4s -> 128B coalesced loads), 3-stage intra-group
// shuffle reduce. b is folded algebraically: p = dot(W[j],Y[i]) + dot(b,Y[i]).
__global__ void __launch_bounds__(256, 5)
main_kernel(const float* __restrict__ A, const float* __restrict__ W,
            const float* __restrict__ b, float* __restrict__ out) {
    __shared__ float qa[8][QCAP];
    __shared__ int   qj[8][QCAP];
    __shared__ int   wcnt[8];
    __shared__ float sp[8];

    const int row  = blockIdx.x;
    const int w    = threadIdx.x >> 5;
    const int lane = threadIdx.x & 31;
    const int gl   = lane & 7;    // lane within 8-lane group
    const int grp  = lane >> 3;   // group 0..3

    const float4* __restrict__ A4 =
        reinterpret_cast<const float4*>(A) + (size_t)row * (GN / 4);
    const float4* __restrict__ W4 = reinterpret_cast<const float4*>(W);
    const float4* __restrict__ B4 = reinterpret_cast<const float4*>(b);

    if (lane == 0) wcnt[w] = 0;
    __syncwarp();

    // Y[row] distributed: lane holds float4 indices {gl, gl+8, gl+16, gl+24}
    // (identical across the 4 groups). Fold b in; accumulate ci = b.Y[row]
    // and rn = ||Y[row]||^2 partials.
    float4 yi[4];
    float ci = 0.f, rn = 0.f;
    #pragma unroll
    for (int i = 0; i < 4; i++) {
        float4 wv = W4[row * 32 + i * 8 + gl];
        float4 bv = B4[i * 8 + gl];
        yi[i].x = wv.x + bv.x; yi[i].y = wv.y + bv.y;
        yi[i].z = wv.z + bv.z; yi[i].w = wv.w + bv.w;
        ci += bv.x * yi[i].x + bv.y * yi[i].y + bv.z * yi[i].z + bv.w * yi[i].w;
        rn += yi[i].x * yi[i].x + yi[i].y * yi[i].y
            + yi[i].z * yi[i].z + yi[i].w * yi[i].w;
    }
    // intra-group reduce (8 lanes cover the full 128-dim row)
    #pragma unroll
    for (int off = 1; off < 8; off <<= 1) {
        ci += __shfl_xor_sync(0xffffffffu, ci, off);
        rn += __shfl_xor_sync(0xffffffffu, rn, off);
    }

    float acc = 0.f;

    auto compact = [&](float4 a4, int f4idx) {
        unsigned nzm = (a4.x > 0.f ? 1u : 0u) | (a4.y > 0.f ? 2u : 0u)
                     | (a4.z > 0.f ? 4u : 0u) | (a4.w > 0.f ? 8u : 0u);
        if (nzm) {
            int n   = __popc(nzm);
            int pos = atomicAdd(&wcnt[w], n);
            if (pos + n <= QCAP) {
                int jb = f4idx * 4;
                if (nzm & 1u) { qa[w][pos] = a4.x; qj[w][pos] = jb;     pos++; }
                if (nzm & 2u) { qa[w][pos] = a4.y; qj[w][pos] = jb + 1; pos++; }
                if (nzm & 4u) { qa[w][pos] = a4.z; qj[w][pos] = jb + 2; pos++; }
                if (nzm & 8u) { qa[w][pos] = a4.w; qj[w][pos] = jb + 3; }
            }
        }
    };

    // drain [from, to), to-from multiple of 4; 4 nonzeros per step
    auto drain = [&](int from, int to) {
        for (int base = from; base < to; base += 4) {
            float a = qa[w][base + grp];   // broadcast within group
            int   j = qj[w][base + grp];
            const float4* yr = W4 + j * 32 + gl;
            float4 y0 = yr[0], y1 = yr[8], y2 = yr[16], y3 = yr[24];
            float p0 = y0.x * yi[0].x + y0.y * yi[0].y + y0.z * yi[0].z + y0.w * yi[0].w;
            float p1 = y1.x * yi[1].x + y1.y * yi[1].y + y1.z * yi[1].z + y1.w * yi[1].w;
            float p2 = y2.x * yi[2].x + y2.y * yi[2].y + y2.z * yi[2].z + y2.w * yi[2].w;
            float p3 = y3.x * yi[3].x + y3.y * yi[3].y + y3.z * yi[3].z + y3.w * yi[3].w;
            float p  = (p0 + p1) + (p2 + p3);
            p += __shfl_xor_sync(0xffffffffu, p, 1);
            p += __shfl_xor_sync(0xffffffffu, p, 2);
            p += __shfl_xor_sync(0xffffffffu, p, 4);
            if (a > 0.f && gl == 0) {      // a<=0 only for pad entries
                float r = a - (p + ci);
                acc = fmaf(0.5f * r, r, acc);
            }
        }
    };

    const int base4 = w * 256;
    float4 av[4];

    // chunk 0 (streaming loads, MLP=4)
    #pragma unroll
    for (int k = 0; k < 4; k++) av[k] = __ldcs(A4 + base4 + k * 32 + lane);
    #pragma unroll
    for (int k = 0; k < 4; k++) compact(av[k], base4 + k * 32 + lane);
    __syncwarp();
    int n0 = wcnt[w] & ~3;

    // issue chunk 1 loads before draining chunk 0 (overlap DRAM with dots)
    #pragma unroll
    for (int k = 0; k < 4; k++) av[k] = __ldcs(A4 + base4 + 128 + k * 32 + lane);
    drain(0, n0);
    #pragma unroll
    for (int k = 0; k < 4; k++) compact(av[k], base4 + 128 + k * 32 + lane);
    __syncwarp();

    int cnt  = min(wcnt[w], QCAP);
    int cntp = (cnt + 3) & ~3;
    if (lane < cntp - cnt) { qa[w][cnt + lane] = -1.f; qj[w][cnt + lane] = 0; }
    __syncwarp();
    drain(n0, cntp);

    // reg loss once per block (warp 0, lane 0 holds group-0-reduced rn)
    if (w == 0 && lane == 0) acc += 0.5f * LMBD * rn;

    // warp reduce (acc lives on gl==0 lanes)
    #pragma unroll
    for (int off = 16; off > 0; off >>= 1)
        acc += __shfl_xor_sync(0xffffffffu, acc, off);
    if (lane == 0) sp[w] = acc;
    __syncthreads();

    if (threadIdx.x == 0) {
        float part = 0.f;
        #pragma unroll
        for (int i = 0; i < 8; i++) part += sp[i];
        atomicAdd(&g_sum, part);
        __threadfence();
        unsigned c = atomicAdd(&g_count, 1u);
        if (c == gridDim.x - 1) {
            float total = atomicExch(&g_sum, 0.f);
            atomicExch(&g_count, 0u);
            out[0] = total;
        }
    }
}

extern "C" void kernel_launch(void* const* d_in, const int* in_sizes, int n_in,
                              void* d_out, int out_size) {
    const float* A = (const float*)d_in[0];
    const float* W = (const float*)d_in[1];
    const float* b = (const float*)d_in[2];
    float* out = (float*)d_out;

    main_kernel<<<GN, 256>>>(A, W, b, out);
}